// round 1
// baseline (speedup 1.0000x reference)
#include <cuda_runtime.h>

#define RES   512
#define NPTS  1024          // 8 curves * 128 steps
#define INVC  5000.0f       // 1/(2*sigma^2), sigma=0.01

// Scratch (static device globals; no runtime allocation)
__device__ float g_x[NPTS];
__device__ float g_y[NPTS];
__device__ float g_Ex[NPTS * RES];   // [k][i]  k-major
__device__ float g_Ey[NPTS * RES];   // [k][j]  k-major

// ---------------------------------------------------------------------------
// Kernel 1: sample the cubic Beziers (de Casteljau, same op order as ref)
// k = c*128 + s,  t = s/127
// ---------------------------------------------------------------------------
__global__ void k_bezier(const float* __restrict__ curves) {
    int k = blockIdx.x * blockDim.x + threadIdx.x;
    if (k >= NPTS) return;
    int c = k >> 7;
    int s = k & 127;
    float t = (float)s * (1.0f / 127.0f);
    const float* P = curves + c * 8;   // curves[c][p][d], row-major (8,4,2)
    float p0x = P[0], p0y = P[1], p1x = P[2], p1y = P[3];
    float p2x = P[4], p2y = P[5], p3x = P[6], p3y = P[7];

    float a01x = p0x + (p1x - p0x) * t;
    float a12x = p1x + (p2x - p1x) * t;
    float a23x = p2x + (p3x - p2x) * t;
    float qax  = a01x + t * (a12x - a01x);
    float qbx  = a12x + t * (a23x - a12x);
    g_x[k] = qax + t * (qbx - qax);

    float a01y = p0y + (p1y - p0y) * t;
    float a12y = p1y + (p2y - p1y) * t;
    float a23y = p2y + (p3y - p2y) * t;
    float qay  = a01y + t * (a12y - a01y);
    float qby  = a12y + t * (a23y - a12y);
    g_y[k] = qay + t * (qby - qay);
}

// ---------------------------------------------------------------------------
// Kernel 2: Gaussian tables  Ex[k][i] = exp(-(x_k - i/512)^2 * 5000), same Ey
// ---------------------------------------------------------------------------
__global__ void k_exp() {
    int idx = blockIdx.x * blockDim.x + threadIdx.x;   // < NPTS*RES
    int k = idx >> 9;          // RES = 512
    int i = idx & (RES - 1);
    float g  = (float)i * (1.0f / RES);
    float dx = g_x[k] - g;
    float dy = g_y[k] - g;
    g_Ex[idx] = __expf(-dx * dx * INVC);
    g_Ey[idx] = __expf(-dy * dy * INVC);
}

// ---------------------------------------------------------------------------
// Kernel 3: out[j][i] = sum_k Ex[k][i] * Ey[k][j]
// Tiles: BM=32 (i), BN=64 (j), BK=32.  grid (16, 8) = 128 blocks ~ 1 wave.
// 256 threads as 16(tx over i) x 16(ty over j); microtile 2(i) x 4(j).
// ---------------------------------------------------------------------------
#define BM 32
#define BN 64
#define BK 32

__global__ __launch_bounds__(256) void k_raster(float* __restrict__ out) {
    __shared__ float exs[BK][BM];
    __shared__ float eys[BK][BN];

    int tx = threadIdx.x & 15;    // i direction
    int ty = threadIdx.x >> 4;    // j direction
    int i0 = blockIdx.x * BM;
    int j0 = blockIdx.y * BN;

    float acc[2][4] = {};

    for (int k0 = 0; k0 < NPTS; k0 += BK) {
        // stage exs: BK*BM = 1024 floats = 256 float4 (one per thread)
        {
            int r  = threadIdx.x >> 3;
            int c4 = (threadIdx.x & 7) * 4;
            float4 v = *(const float4*)&g_Ex[(k0 + r) * RES + i0 + c4];
            *(float4*)&exs[r][c4] = v;
        }
        // stage eys: BK*BN = 2048 floats = 512 float4 (two per thread)
        #pragma unroll
        for (int rr = 0; rr < 2; rr++) {
            int e  = threadIdx.x + rr * 256;
            int r  = e >> 4;
            int c4 = (e & 15) * 4;
            float4 v = *(const float4*)&g_Ey[(k0 + r) * RES + j0 + c4];
            *(float4*)&eys[r][c4] = v;
        }
        __syncthreads();

        #pragma unroll
        for (int kk = 0; kk < BK; kk++) {
            float2 ex = *(const float2*)&exs[kk][tx * 2];
            float4 ey = *(const float4*)&eys[kk][ty * 4];
            acc[0][0] += ex.x * ey.x;  acc[0][1] += ex.x * ey.y;
            acc[0][2] += ex.x * ey.z;  acc[0][3] += ex.x * ey.w;
            acc[1][0] += ex.y * ey.x;  acc[1][1] += ex.y * ey.y;
            acc[1][2] += ex.y * ey.z;  acc[1][3] += ex.y * ey.w;
        }
        __syncthreads();
    }

    int i = i0 + tx * 2;
    int j = j0 + ty * 4;
    #pragma unroll
    for (int jj = 0; jj < 4; jj++) {
        float2 v = make_float2(acc[0][jj], acc[1][jj]);
        *(float2*)&out[(j + jj) * RES + i] = v;
    }
}

// ---------------------------------------------------------------------------
extern "C" void kernel_launch(void* const* d_in, const int* in_sizes, int n_in,
                              void* d_out, int out_size) {
    const float* curves = (const float*)d_in[0];
    float* out = (float*)d_out;

    k_bezier<<<4, 256>>>(curves);
    k_exp<<<(NPTS * RES) / 256, 256>>>();
    dim3 grid(RES / BM, RES / BN);
    k_raster<<<grid, 256>>>(out);
}

// round 4
// speedup vs baseline: 2.0661x; 2.0661x over previous
#include <cuda_runtime.h>
#include <cstdint>

#define RES    512
#define NPTS   1024          // 8 curves * 128 steps
#define INVC   5000.0f       // 1/(2*sigma^2), sigma=0.01

#define BM     128           // i per block
#define BN     128           // j per block
#define BK     32            // k per staging chunk
#define SPLITK 8
#define KCHUNK (NPTS / SPLITK)   // 128

// Scratch (static device globals; no runtime allocation)
__device__ float g_Ex[NPTS * RES];              // [k][i]  k-major
__device__ float g_Ey[NPTS * RES];              // [k][j]  k-major
__device__ float g_part[SPLITK * RES * RES];    // split-K partials, 8 MB

// packed f32x2 FMA: d = a*b + d  (element-wise on 2 packed fp32)
#define FMA_F32X2(d, a, b) \
    asm("fma.rn.f32x2 %0, %1, %2, %0;" : "+l"(d) : "l"(a), "l"(b))

// ---------------------------------------------------------------------------
// Kernel 1: fused Bezier sampling + Gaussian tables.
// One thread handles one k and 4 grid positions (float4 stores).
//   Ex[k][i] = exp(-(x_k - i/512)^2 * 5000),  same for Ey with y_k.
// ---------------------------------------------------------------------------
__global__ void k_exp(const float* __restrict__ curves) {
    int tid = blockIdx.x * blockDim.x + threadIdx.x;   // < NPTS * RES/4
    int k  = tid >> 7;            // RES/4 = 128 groups per k
    int i4 = (tid & 127) << 2;

    // de Casteljau (same op order as reference)
    int c = k >> 7;
    int s = k & 127;
    float t = (float)s * (1.0f / 127.0f);
    const float* P = curves + c * 8;
    float p0x = __ldg(P+0), p0y = __ldg(P+1), p1x = __ldg(P+2), p1y = __ldg(P+3);
    float p2x = __ldg(P+4), p2y = __ldg(P+5), p3x = __ldg(P+6), p3y = __ldg(P+7);

    float a01 = p0x + (p1x - p0x) * t;
    float a12 = p1x + (p2x - p1x) * t;
    float a23 = p2x + (p3x - p2x) * t;
    float qa  = a01 + t * (a12 - a01);
    float qb  = a12 + t * (a23 - a12);
    float xk  = qa + t * (qb - qa);

    a01 = p0y + (p1y - p0y) * t;
    a12 = p1y + (p2y - p1y) * t;
    a23 = p2y + (p3y - p2y) * t;
    qa  = a01 + t * (a12 - a01);
    qb  = a12 + t * (a23 - a12);
    float yk = qa + t * (qb - qa);

    float4 ex, ey;
    float g0 = (float)i4 * (1.0f / RES);
    const float step = 1.0f / RES;
    {
        float d;
        d = xk - (g0 + 0.f*step); ex.x = __expf(-d * d * INVC);
        d = xk - (g0 + 1.f*step); ex.y = __expf(-d * d * INVC);
        d = xk - (g0 + 2.f*step); ex.z = __expf(-d * d * INVC);
        d = xk - (g0 + 3.f*step); ex.w = __expf(-d * d * INVC);
        d = yk - (g0 + 0.f*step); ey.x = __expf(-d * d * INVC);
        d = yk - (g0 + 1.f*step); ey.y = __expf(-d * d * INVC);
        d = yk - (g0 + 2.f*step); ey.z = __expf(-d * d * INVC);
        d = yk - (g0 + 3.f*step); ey.w = __expf(-d * d * INVC);
    }
    *(float4*)&g_Ex[k * RES + i4] = ex;
    *(float4*)&g_Ey[k * RES + i4] = ey;
}

// ---------------------------------------------------------------------------
// Kernel 2: split-K GEMM partials.
//   part[z][j][i] = sum_{k in chunk z} Ex[k][i] * Ey[k][j]
// Block tile 128(i) x 128(j) x KCHUNK, 256 threads (16 tx over i, 16 ty over j),
// microtile 8x8, inner math in packed f32x2 (pairs along i).
// ey is stored DUPLICATED in smem so ey f32x2 operands come straight from LDS
// (broadcast across the warp -> crossbar-free).
// ---------------------------------------------------------------------------
__global__ __launch_bounds__(256) void k_raster() {
    __shared__ float exs[BK][BM];        // 16 KB
    __shared__ float eyd[BK][2 * BN];    // 32 KB (each value duplicated)

    const int tx = threadIdx.x & 15;     // i direction
    const int ty = threadIdx.x >> 4;     // j direction
    const int i0 = blockIdx.x * BM;
    const int j0 = blockIdx.y * BN;
    const int kbase = blockIdx.z * KCHUNK;

    unsigned long long acc[4][8];        // [i-pair][j]
    #pragma unroll
    for (int a = 0; a < 4; a++)
        #pragma unroll
        for (int b = 0; b < 8; b++) acc[a][b] = 0ull;

    for (int k0 = kbase; k0 < kbase + KCHUNK; k0 += BK) {
        // ---- stage exs: BK*BM = 4096 floats = 1024 float4, 4 per thread
        #pragma unroll
        for (int r = 0; r < 4; r++) {
            int f   = threadIdx.x + r * 256;
            int row = f >> 5;            // 32 float4 per row
            int c4  = (f & 31) << 2;
            *(float4*)&exs[row][c4] =
                *(const float4*)&g_Ex[(k0 + row) * RES + i0 + c4];
        }
        // ---- stage eyd (duplicated): read 1024 float4, write 2048
        #pragma unroll
        for (int r = 0; r < 4; r++) {
            int f   = threadIdx.x + r * 256;
            int row = f >> 5;
            int c4  = (f & 31) << 2;
            float4 v = *(const float4*)&g_Ey[(k0 + row) * RES + j0 + c4];
            float4 lo = make_float4(v.x, v.x, v.y, v.y);
            float4 hi = make_float4(v.z, v.z, v.w, v.w);
            *(float4*)&eyd[row][2 * c4]     = lo;
            *(float4*)&eyd[row][2 * c4 + 4] = hi;
        }
        __syncthreads();

        #pragma unroll
        for (int kk = 0; kk < BK; kk++) {
            // ex: 8 consecutive i values = 4 natural f32x2 pairs
            ulonglong2 exa = *(const ulonglong2*)&exs[kk][tx * 8];
            ulonglong2 exb = *(const ulonglong2*)&exs[kk][tx * 8 + 4];
            unsigned long long exp2[4] = {exa.x, exa.y, exb.x, exb.y};
            // ey: 8 duplicated pairs (broadcast LDS)
            ulonglong2 e0 = *(const ulonglong2*)&eyd[kk][ty * 16];
            ulonglong2 e1 = *(const ulonglong2*)&eyd[kk][ty * 16 + 4];
            ulonglong2 e2 = *(const ulonglong2*)&eyd[kk][ty * 16 + 8];
            ulonglong2 e3 = *(const ulonglong2*)&eyd[kk][ty * 16 + 12];
            unsigned long long eyp[8] = {e0.x, e0.y, e1.x, e1.y,
                                         e2.x, e2.y, e3.x, e3.y};
            #pragma unroll
            for (int jj = 0; jj < 8; jj++)
                #pragma unroll
                for (int ip = 0; ip < 4; ip++)
                    FMA_F32X2(acc[ip][jj], exp2[ip], eyp[jj]);
        }
        __syncthreads();
    }

    // ---- write partials: 8 rows (j) x 32 contiguous bytes (i), coalesced
    float* base = g_part + (size_t)blockIdx.z * RES * RES;
    const int i = i0 + tx * 8;
    #pragma unroll
    for (int jj = 0; jj < 8; jj++) {
        int j = j0 + ty * 8 + jj;
        ulonglong2 v0; v0.x = acc[0][jj]; v0.y = acc[1][jj];
        ulonglong2 v1; v1.x = acc[2][jj]; v1.y = acc[3][jj];
        *(ulonglong2*)&base[j * RES + i]     = v0;
        *(ulonglong2*)&base[j * RES + i + 4] = v1;
    }
}

// ---------------------------------------------------------------------------
// Kernel 3: reduce the SPLITK partials into the output.
// Two independent accumulator chains to expose ILP; DRAM-bound regardless.
// ---------------------------------------------------------------------------
__global__ void k_reduce(float* __restrict__ out) {
    int t = blockIdx.x * blockDim.x + threadIdx.x;   // < RES*RES/4
    const float* __restrict__ p = g_part;
    float4 s0 = make_float4(0.f, 0.f, 0.f, 0.f);
    float4 s1 = make_float4(0.f, 0.f, 0.f, 0.f);
    #pragma unroll
    for (int z = 0; z < SPLITK; z += 2) {
        float4 a = *(const float4*)&p[(size_t)z       * RES * RES + t * 4];
        float4 b = *(const float4*)&p[(size_t)(z + 1) * RES * RES + t * 4];
        s0.x += a.x; s0.y += a.y; s0.z += a.z; s0.w += a.w;
        s1.x += b.x; s1.y += b.y; s1.z += b.z; s1.w += b.w;
    }
    float4 s = make_float4(s0.x + s1.x, s0.y + s1.y, s0.z + s1.z, s0.w + s1.w);
    *(float4*)&out[t * 4] = s;
}

// ---------------------------------------------------------------------------
extern "C" void kernel_launch(void* const* d_in, const int* in_sizes, int n_in,
                              void* d_out, int out_size) {
    const float* curves = (const float*)d_in[0];
    float* out = (float*)d_out;

    k_exp<<<(NPTS * RES / 4) / 256, 256>>>(curves);
    dim3 grid(RES / BM, RES / BN, SPLITK);
    k_raster<<<grid, 256>>>();
    k_reduce<<<(RES * RES / 4) / 256, 256>>>(out);
}

// round 5
// speedup vs baseline: 2.4339x; 1.1780x over previous
#include <cuda_runtime.h>
#include <cstdint>

#define RES   512
#define NPTS  1024           // 8 curves * 128 steps
#define INVC  5000.0f        // 1/(2*sigma^2), sigma=0.01

// Band: exp(-5000 d^2) < 1e-34 for |d| > 64/512. Table computed within +-66
// cells; tile gather accepts +-70 (strict superset incl. 4-col group width).
#define BAND_TAB  66.0f
#define BAND_ACC  70.0f

#define TI  32               // tile i
#define TJ  32               // tile j
#define BKT 16               // gathered k per staging chunk

// Scratch (static device globals; no runtime allocation)
__device__ float g_Ex[NPTS * RES];   // [k][i]  k-major (zero outside band)
__device__ float g_Ey[NPTS * RES];   // [k][j]  k-major (zero outside band)
__device__ float g_xi[NPTS];         // x_k * 512 (cell coords)
__device__ float g_yi[NPTS];         // y_k * 512

// ---------------------------------------------------------------------------
// Kernel 1: fused Bezier sampling + band-limited Gaussian tables.
// Thread handles one k and a 4-column group; exp only computed in-band.
// ---------------------------------------------------------------------------
__global__ void k_exp(const float* __restrict__ curves) {
    int tid = blockIdx.x * blockDim.x + threadIdx.x;   // < NPTS * RES/4
    int k  = tid >> 7;            // RES/4 = 128 groups per k
    int i4 = (tid & 127) << 2;

    // de Casteljau (same op order as reference)
    int c = k >> 7;
    int s = k & 127;
    float t = (float)s * (1.0f / 127.0f);
    const float* P = curves + c * 8;
    float p0x = __ldg(P+0), p0y = __ldg(P+1), p1x = __ldg(P+2), p1y = __ldg(P+3);
    float p2x = __ldg(P+4), p2y = __ldg(P+5), p3x = __ldg(P+6), p3y = __ldg(P+7);

    float a01 = p0x + (p1x - p0x) * t;
    float a12 = p1x + (p2x - p1x) * t;
    float a23 = p2x + (p3x - p2x) * t;
    float qa  = a01 + t * (a12 - a01);
    float qb  = a12 + t * (a23 - a12);
    float xk  = qa + t * (qb - qa);

    a01 = p0y + (p1y - p0y) * t;
    a12 = p1y + (p2y - p1y) * t;
    a23 = p2y + (p3y - p2y) * t;
    qa  = a01 + t * (a12 - a01);
    qb  = a12 + t * (a23 - a12);
    float yk = qa + t * (qb - qa);

    float xi = xk * (float)RES;
    float yi = yk * (float)RES;
    if ((tid & 127) == 0) { g_xi[k] = xi; g_yi[k] = yi; }

    float g0 = (float)i4 * (1.0f / RES);
    const float step = 1.0f / RES;
    float4 zero = make_float4(0.f, 0.f, 0.f, 0.f);

    float4 ex = zero;
    if (xi >= (float)i4 - BAND_TAB && xi <= (float)(i4 + 3) + BAND_TAB) {
        float d;
        d = xk - (g0 + 0.f*step); ex.x = __expf(-d * d * INVC);
        d = xk - (g0 + 1.f*step); ex.y = __expf(-d * d * INVC);
        d = xk - (g0 + 2.f*step); ex.z = __expf(-d * d * INVC);
        d = xk - (g0 + 3.f*step); ex.w = __expf(-d * d * INVC);
    }
    float4 ey = zero;
    if (yi >= (float)i4 - BAND_TAB && yi <= (float)(i4 + 3) + BAND_TAB) {
        float d;
        d = yk - (g0 + 0.f*step); ey.x = __expf(-d * d * INVC);
        d = yk - (g0 + 1.f*step); ey.y = __expf(-d * d * INVC);
        d = yk - (g0 + 2.f*step); ey.z = __expf(-d * d * INVC);
        d = yk - (g0 + 3.f*step); ey.w = __expf(-d * d * INVC);
    }
    *(float4*)&g_Ex[k * RES + i4] = ex;
    *(float4*)&g_Ey[k * RES + i4] = ey;
}

// ---------------------------------------------------------------------------
// Kernel 2: band-gathered tile GEMM.
// One block per 32x32 output tile. Deterministic order-preserving compaction
// of contributing k's, then a double-buffered smem GEMM over gathered rows.
//   out[j][i] = sum_{k in list} Ex[k][i] * Ey[k][j]
// ---------------------------------------------------------------------------
__global__ __launch_bounds__(256) void k_tile(float* __restrict__ out) {
    __shared__ float sxi[NPTS];
    __shared__ float syi[NPTS];
    __shared__ unsigned short klist[NPTS];
    __shared__ float exs[2][BKT][TI];
    __shared__ float eys[2][BKT][TJ];
    __shared__ int warp_cnt[8], warp_off[8], s_total;

    const int tid = threadIdx.x;
    const int i0 = blockIdx.x * TI;
    const int j0 = blockIdx.y * TJ;

    // ---- load point centers
    #pragma unroll
    for (int r = 0; r < 4; r++) {
        int k = tid + r * 256;
        sxi[k] = g_xi[k];
        syi[k] = g_yi[k];
    }
    if (tid == 0) s_total = 0;
    __syncthreads();

    // ---- deterministic, order-preserving compaction of contributing k's
    const float ilo = (float)i0 - BAND_ACC, ihi = (float)(i0 + TI - 1) + BAND_ACC;
    const float jlo = (float)j0 - BAND_ACC, jhi = (float)(j0 + TJ - 1) + BAND_ACC;
    const int lane = tid & 31, wid = tid >> 5;
    for (int c = 0; c < 4; c++) {
        int k = c * 256 + tid;
        bool ok = (sxi[k] >= ilo) && (sxi[k] <= ihi) &&
                  (syi[k] >= jlo) && (syi[k] <= jhi);
        unsigned m = __ballot_sync(0xffffffffu, ok);
        if (lane == 0) warp_cnt[wid] = __popc(m);
        __syncthreads();
        if (tid == 0) {
            int ssum = s_total;
            #pragma unroll
            for (int w = 0; w < 8; w++) { warp_off[w] = ssum; ssum += warp_cnt[w]; }
            s_total = ssum;
        }
        __syncthreads();
        if (ok)
            klist[warp_off[wid] + __popc(m & ((1u << lane) - 1u))] =
                (unsigned short)k;
        __syncthreads();
    }
    const int nk = s_total;
    const int nc = (nk + BKT - 1) / BKT;

    // ---- gathered GEMM, double-buffered staging
    const int tx = tid & 7;       // i: 4 columns each
    const int ty = tid >> 3;      // j: 1 row each (32)
    const int r  = tid >> 4;      // staged row within chunk (16 rows)
    const int q  = tid & 15;      // q<8: ex float4, q>=8: ey float4
    float4 acc = make_float4(0.f, 0.f, 0.f, 0.f);

    // stage chunk 0
    {
        float4 v = make_float4(0.f, 0.f, 0.f, 0.f);
        if (r < nk) {
            int k = klist[r];
            const float* src = (q < 8)
                ? &g_Ex[k * RES + i0 + (q << 2)]
                : &g_Ey[k * RES + j0 + ((q - 8) << 2)];
            v = *(const float4*)src;
        }
        if (q < 8) *(float4*)&exs[0][r][q << 2] = v;
        else       *(float4*)&eys[0][r][(q - 8) << 2] = v;
    }
    __syncthreads();

    for (int c = 0; c < nc; c++) {
        int buf = c & 1;
        bool has_next = (c + 1 < nc);
        // prefetch next chunk into registers (overlaps compute)
        float4 v = make_float4(0.f, 0.f, 0.f, 0.f);
        if (has_next) {
            int kk = (c + 1) * BKT + r;
            if (kk < nk) {
                int k = klist[kk];
                const float* src = (q < 8)
                    ? &g_Ex[k * RES + i0 + (q << 2)]
                    : &g_Ey[k * RES + j0 + ((q - 8) << 2)];
                v = *(const float4*)src;
            }
        }
        // compute on current buffer
        #pragma unroll
        for (int kk = 0; kk < BKT; kk++) {
            float   ey = eys[buf][kk][ty];
            float4  ex = *(const float4*)&exs[buf][kk][tx << 2];
            acc.x += ex.x * ey;
            acc.y += ex.y * ey;
            acc.z += ex.z * ey;
            acc.w += ex.w * ey;
        }
        if (has_next) {
            __syncthreads();
            if (q < 8) *(float4*)&exs[buf ^ 1][r][q << 2] = v;
            else       *(float4*)&eys[buf ^ 1][r][(q - 8) << 2] = v;
        }
        __syncthreads();
    }

    // ---- write tile (coalesced: 8 lanes * 16B = 128B per row)
    *(float4*)&out[(j0 + ty) * RES + i0 + (tx << 2)] = acc;
}

// ---------------------------------------------------------------------------
extern "C" void kernel_launch(void* const* d_in, const int* in_sizes, int n_in,
                              void* d_out, int out_size) {
    const float* curves = (const float*)d_in[0];
    float* out = (float*)d_out;

    k_exp<<<(NPTS * RES / 4) / 256, 256>>>(curves);
    dim3 grid(RES / TI, RES / TJ);
    k_tile<<<grid, 256>>>(out);
}

// round 6
// speedup vs baseline: 2.8548x; 1.1729x over previous
#include <cuda_runtime.h>
#include <cstdint>

#define RES   512
#define NPTS  1024            // 8 curves * 128 steps
// exponent in cell units: (xk - i/512)^2*5000 == (xi - i)^2 * (5000/2^18)
#define INVC_CELL 0.019073486328125f   // 5000 / 262144, exact in fp32
#define BAND  70.0f           // exp(-5000 d^2) < 4e-41 beyond 70/512

#define TI  32                // tile i
#define TJ  32                // tile j
#define BKC 32                // gathered k per staging chunk

// ---------------------------------------------------------------------------
// Single fused kernel. One block per 32x32 output tile (grid 16x16).
//  1. each thread evaluates 4 Bezier sample points (k = 4*tid .. 4*tid+3)
//  2. order-preserving compaction of points within +-BAND cells of the tile
//  3. chunked: recompute ex/ey via __expf into smem, rank-1 accumulate
//  4. write tile
// No global scratch, no inter-kernel dependency, no gathers from big tables.
// ---------------------------------------------------------------------------
__global__ __launch_bounds__(256) void k_fused(const float* __restrict__ curves,
                                               float* __restrict__ out) {
    __shared__ float sx[NPTS];            // unit coords of sample points
    __shared__ float sy[NPTS];
    __shared__ unsigned short klist[NPTS];
    __shared__ float sex[BKC][TI];        // staged ex values (4 KB)
    __shared__ float sey[BKC][TJ];        // staged ey values (4 KB)
    __shared__ int wsum[8], woff[8], s_total;

    const int tid  = threadIdx.x;
    const int lane = tid & 31, wid = tid >> 5;
    const int i0 = blockIdx.x * TI;
    const int j0 = blockIdx.y * TJ;

    // ---- 1. Bezier points: 4 per thread (same op order as reference) ------
    float xs[4], ys[4];
    const int kb = tid * 4;
    {
        const int c = kb >> 7;                 // 4 consecutive k share a curve
        const float* P = curves + c * 8;
        float p0x = __ldg(P+0), p0y = __ldg(P+1), p1x = __ldg(P+2), p1y = __ldg(P+3);
        float p2x = __ldg(P+4), p2y = __ldg(P+5), p3x = __ldg(P+6), p3y = __ldg(P+7);
        #pragma unroll
        for (int u = 0; u < 4; u++) {
            float t = (float)((kb + u) & 127) * (1.0f / 127.0f);
            float a01 = p0x + (p1x - p0x) * t;
            float a12 = p1x + (p2x - p1x) * t;
            float a23 = p2x + (p3x - p2x) * t;
            float qa  = a01 + t * (a12 - a01);
            float qb  = a12 + t * (a23 - a12);
            xs[u] = qa + t * (qb - qa);
            a01 = p0y + (p1y - p0y) * t;
            a12 = p1y + (p2y - p1y) * t;
            a23 = p2y + (p3y - p2y) * t;
            qa  = a01 + t * (a12 - a01);
            qb  = a12 + t * (a23 - a12);
            ys[u] = qa + t * (qb - qa);
            sx[kb + u] = xs[u];
            sy[kb + u] = ys[u];
        }
    }

    // ---- 2. acceptance + single-pass order-preserving compaction ----------
    const float ilo = (float)i0 - BAND, ihi = (float)(i0 + TI - 1) + BAND;
    const float jlo = (float)j0 - BAND, jhi = (float)(j0 + TJ - 1) + BAND;
    bool ok[4];
    int cnt = 0;
    #pragma unroll
    for (int u = 0; u < 4; u++) {
        float xi = xs[u] * (float)RES;
        float yi = ys[u] * (float)RES;
        ok[u] = (xi >= ilo) & (xi <= ihi) & (yi >= jlo) & (yi <= jhi);
        cnt += ok[u] ? 1 : 0;
    }
    int inc = cnt;                               // warp inclusive scan
    #pragma unroll
    for (int d = 1; d < 32; d <<= 1) {
        int n = __shfl_up_sync(0xffffffffu, inc, d);
        if (lane >= d) inc += n;
    }
    if (lane == 31) wsum[wid] = inc;
    __syncthreads();
    if (tid == 0) {
        int s = 0;
        #pragma unroll
        for (int w = 0; w < 8; w++) { woff[w] = s; s += wsum[w]; }
        s_total = s;
    }
    __syncthreads();
    int off = woff[wid] + inc - cnt;
    #pragma unroll
    for (int u = 0; u < 4; u++)
        if (ok[u]) klist[off++] = (unsigned short)(kb + u);
    __syncthreads();
    const int nk = s_total;

    // ---- 3. chunked recompute + rank-1 accumulate -------------------------
    const int r  = tid >> 3;       // staging: chunk row 0..31
    const int q  = tid & 7;        // staging: 4-col group (ex and ey)
    const int tx = tid & 7;        // compute: 4 i's
    const int ty = tid >> 3;       // compute: 1 j
    float4 acc = make_float4(0.f, 0.f, 0.f, 0.f);

    for (int c = 0; c < nk; c += BKC) {
        float4 ev = make_float4(0.f, 0.f, 0.f, 0.f);
        float4 fv = make_float4(0.f, 0.f, 0.f, 0.f);
        int row = c + r;
        if (row < nk) {
            int k = klist[row];
            float xi = sx[k] * (float)RES;
            float yi = sy[k] * (float)RES;
            float bi = (float)(i0 + q * 4);
            float bj = (float)(j0 + q * 4);
            float d;
            d = xi - (bi + 0.f); ev.x = __expf(-d * d * INVC_CELL);
            d = xi - (bi + 1.f); ev.y = __expf(-d * d * INVC_CELL);
            d = xi - (bi + 2.f); ev.z = __expf(-d * d * INVC_CELL);
            d = xi - (bi + 3.f); ev.w = __expf(-d * d * INVC_CELL);
            d = yi - (bj + 0.f); fv.x = __expf(-d * d * INVC_CELL);
            d = yi - (bj + 1.f); fv.y = __expf(-d * d * INVC_CELL);
            d = yi - (bj + 2.f); fv.z = __expf(-d * d * INVC_CELL);
            d = yi - (bj + 3.f); fv.w = __expf(-d * d * INVC_CELL);
        }
        __syncthreads();                       // prev chunk's compute done
        *(float4*)&sex[r][q * 4] = ev;
        *(float4*)&sey[r][q * 4] = fv;
        __syncthreads();

        #pragma unroll
        for (int kk = 0; kk < BKC; kk++) {
            float  ey = sey[kk][ty];
            float4 ex = *(const float4*)&sex[kk][tx * 4];
            acc.x += ex.x * ey;
            acc.y += ex.y * ey;
            acc.z += ex.z * ey;
            acc.w += ex.w * ey;
        }
    }

    // ---- 4. write tile (out[j][i], coalesced float4) ----------------------
    *(float4*)&out[(j0 + ty) * RES + i0 + tx * 4] = acc;
}

// ---------------------------------------------------------------------------
extern "C" void kernel_launch(void* const* d_in, const int* in_sizes, int n_in,
                              void* d_out, int out_size) {
    const float* curves = (const float*)d_in[0];
    float* out = (float*)d_out;
    dim3 grid(RES / TI, RES / TJ);
    k_fused<<<grid, 256>>>(curves, out);
}

// round 8
// speedup vs baseline: 3.8043x; 1.3326x over previous
#include <cuda_runtime.h>
#include <cstdint>

#define RES   512
#define NPTS  1024            // 8 curves * 128 steps
// exponent in cell units: (xk - i/512)^2*5000 == (xi - i)^2 * (5000/2^18)
#define INVC_CELL 0.019073486328125f   // 5000 / 262144, exact in fp32
// Dropped terms <= exp(-5000*(36/512)^2) = 1.8e-11 each; global-norm metric
// (empirically identical rel_err for dense vs BAND=70) -> safe at 1e-3.
#define BAND  36.0f

#define TI  32                // tile i
#define TJ  32                // tile j
#define BKC 32                // gathered k per staging chunk

// packed f32x2 FMA: d = a*b + d (element-wise on 2 packed fp32)
#define FMA_F32X2(d, a, b) \
    asm("fma.rn.f32x2 %0, %1, %2, %0;" : "+l"(d) : "l"(a), "l"(b))

// ---------------------------------------------------------------------------
// Single fused kernel. One block per 32x32 output tile (grid 16x16).
//  1. each thread evaluates 4 Bezier sample points
//  2. order-preserving compaction of points within +-BAND cells of the tile
//  3. chunked: recompute ex/ey via __expf into smem (ey duplicated for f32x2),
//     rank-1 accumulate with packed FMA2
//  4. write tile
// ---------------------------------------------------------------------------
__global__ __launch_bounds__(256) void k_fused(const float* __restrict__ curves,
                                               float* __restrict__ out) {
    __shared__ float sx[NPTS];            // unit coords of sample points
    __shared__ float sy[NPTS];
    __shared__ unsigned short klist[NPTS];
    __shared__ float sex[BKC][TI];        // staged ex values (4 KB)
    __shared__ float seyd[BKC][2 * TJ];   // staged ey, duplicated (8 KB)
    __shared__ int wsum[8], woff[8], s_total;

    const int tid  = threadIdx.x;
    const int lane = tid & 31, wid = tid >> 5;
    const int i0 = blockIdx.x * TI;
    const int j0 = blockIdx.y * TJ;

    // ---- 1. Bezier points: 4 per thread (same op order as reference) ------
    float xs[4], ys[4];
    const int kb = tid * 4;
    {
        const int c = kb >> 7;                 // 4 consecutive k share a curve
        const float* P = curves + c * 8;
        float p0x = __ldg(P+0), p0y = __ldg(P+1), p1x = __ldg(P+2), p1y = __ldg(P+3);
        float p2x = __ldg(P+4), p2y = __ldg(P+5), p3x = __ldg(P+6), p3y = __ldg(P+7);
        #pragma unroll
        for (int u = 0; u < 4; u++) {
            float t = (float)((kb + u) & 127) * (1.0f / 127.0f);
            float a01 = p0x + (p1x - p0x) * t;
            float a12 = p1x + (p2x - p1x) * t;
            float a23 = p2x + (p3x - p2x) * t;
            float qa  = a01 + t * (a12 - a01);
            float qb  = a12 + t * (a23 - a12);
            xs[u] = qa + t * (qb - qa);
            a01 = p0y + (p1y - p0y) * t;
            a12 = p1y + (p2y - p1y) * t;
            a23 = p2y + (p3y - p2y) * t;
            qa  = a01 + t * (a12 - a01);
            qb  = a12 + t * (a23 - a12);
            ys[u] = qa + t * (qb - qa);
            sx[kb + u] = xs[u];
            sy[kb + u] = ys[u];
        }
    }

    // ---- 2. acceptance + single-pass order-preserving compaction ----------
    const float ilo = (float)i0 - BAND, ihi = (float)(i0 + TI - 1) + BAND;
    const float jlo = (float)j0 - BAND, jhi = (float)(j0 + TJ - 1) + BAND;
    bool ok[4];
    int cnt = 0;
    #pragma unroll
    for (int u = 0; u < 4; u++) {
        float xi = xs[u] * (float)RES;
        float yi = ys[u] * (float)RES;
        ok[u] = (xi >= ilo) & (xi <= ihi) & (yi >= jlo) & (yi <= jhi);
        cnt += ok[u] ? 1 : 0;
    }
    int inc = cnt;                               // warp inclusive scan
    #pragma unroll
    for (int d = 1; d < 32; d <<= 1) {
        int n = __shfl_up_sync(0xffffffffu, inc, d);
        if (lane >= d) inc += n;
    }
    if (lane == 31) wsum[wid] = inc;
    __syncthreads();
    if (tid == 0) {
        int s = 0;
        #pragma unroll
        for (int w = 0; w < 8; w++) { woff[w] = s; s += wsum[w]; }
        s_total = s;
    }
    __syncthreads();
    int off = woff[wid] + inc - cnt;
    #pragma unroll
    for (int u = 0; u < 4; u++)
        if (ok[u]) klist[off++] = (unsigned short)(kb + u);
    __syncthreads();
    const int nk = s_total;

    // ---- 3. chunked recompute + packed rank-1 accumulate ------------------
    const int r  = tid >> 3;       // staging: chunk row 0..31
    const int q  = tid & 7;        // staging: 4-col group (ex and ey)
    const int tx = tid & 7;        // compute: 4 i's (2 f32x2 pairs)
    const int ty = tid >> 3;       // compute: 1 j
    unsigned long long acc0 = 0ull, acc1 = 0ull;

    for (int c = 0; c < nk; c += BKC) {
        float4 ev = make_float4(0.f, 0.f, 0.f, 0.f);
        float4 fv = make_float4(0.f, 0.f, 0.f, 0.f);
        int row = c + r;
        if (row < nk) {
            int k = klist[row];
            float xi = sx[k] * (float)RES;
            float yi = sy[k] * (float)RES;
            float bi = (float)(i0 + q * 4);
            float bj = (float)(j0 + q * 4);
            float d;
            d = xi - (bi + 0.f); ev.x = __expf(-d * d * INVC_CELL);
            d = xi - (bi + 1.f); ev.y = __expf(-d * d * INVC_CELL);
            d = xi - (bi + 2.f); ev.z = __expf(-d * d * INVC_CELL);
            d = xi - (bi + 3.f); ev.w = __expf(-d * d * INVC_CELL);
            d = yi - (bj + 0.f); fv.x = __expf(-d * d * INVC_CELL);
            d = yi - (bj + 1.f); fv.y = __expf(-d * d * INVC_CELL);
            d = yi - (bj + 2.f); fv.z = __expf(-d * d * INVC_CELL);
            d = yi - (bj + 3.f); fv.w = __expf(-d * d * INVC_CELL);
        }
        __syncthreads();                       // prev chunk's compute done
        *(float4*)&sex[r][q * 4] = ev;
        *(float4*)&seyd[r][q * 8]     = make_float4(fv.x, fv.x, fv.y, fv.y);
        *(float4*)&seyd[r][q * 8 + 4] = make_float4(fv.z, fv.z, fv.w, fv.w);
        __syncthreads();

        #pragma unroll
        for (int kk = 0; kk < BKC; kk++) {
            unsigned long long eyp =
                *(const unsigned long long*)&seyd[kk][ty * 2];
            ulonglong2 exp2 = *(const ulonglong2*)&sex[kk][tx * 4];
            FMA_F32X2(acc0, exp2.x, eyp);
            FMA_F32X2(acc1, exp2.y, eyp);
        }
    }

    // ---- 4. write tile (out[j][i], coalesced 16B) -------------------------
    ulonglong2 v; v.x = acc0; v.y = acc1;
    *(ulonglong2*)&out[(j0 + ty) * RES + i0 + tx * 4] = v;
}

// ---------------------------------------------------------------------------
extern "C" void kernel_launch(void* const* d_in, const int* in_sizes, int n_in,
                              void* d_out, int out_size) {
    const float* curves = (const float*)d_in[0];
    float* out = (float*)d_out;
    dim3 grid(RES / TI, RES / TJ);
    k_fused<<<grid, 256>>>(curves, out);
}